// round 15
// baseline (speedup 1.0000x reference)
#include <cuda_runtime.h>
#include <cstdint>

#define THREADS 128
#define CPB     80
#define STAGES  4
#define PRED_F  (CPB * 30)        // 2400 floats (9600 B)
#define TARG_F  (CPB * 25)        // 2000 floats (8000 B)
#define PF4     (PRED_F / 4)      // 600 float4
#define TF4     (TARG_F / 4)      // 500 float4
#define MAX_RES 444               // 3 blocks/SM x 148 SMs
#define MAX_PART 2048

__device__ float g_partials[MAX_PART];
__device__ unsigned int g_count = 0;   // wraps to 0 each replay via atomicInc

__device__ __forceinline__ void cp16_l2(unsigned smem_addr, const void* gptr) {
    asm volatile("cp.async.cg.shared.global.L2::256B [%0], [%1], 16;"
                 :: "r"(smem_addr), "l"(gptr) : "memory");
}
__device__ __forceinline__ void cp_commit() {
    asm volatile("cp.async.commit_group;" ::: "memory");
}
template <int N>
__device__ __forceinline__ void cp_wait() {
    asm volatile("cp.async.wait_group %0;" :: "n"(N) : "memory");
}

__device__ __forceinline__ float cell_loss(const float* P, const float* T) {
    float c1 = P[4], c2 = P[9], c = T[4];
    bool present = (c == 1.0f);
    bool r1 = (c1 > c2);
    if (present) {
        float dobj = (r1 ? c1 : c2) - c;
        float loss = dobj * dobj;
        float cls = 0.0f;
        #pragma unroll
        for (int i = 0; i < 20; ++i) {
            float d = P[10 + i] - T[5 + i];
            cls = fmaf(d, d, cls);
        }
        int o = r1 ? 0 : 5;
        float box = 0.0f;
        #pragma unroll
        for (int i = 0; i < 2; ++i) {
            float d = P[o + i] - T[i];
            box = fmaf(d, d, box);
        }
        #pragma unroll
        for (int i = 0; i < 2; ++i) {
            float d = sqrtf(P[o + 2 + i]) - sqrtf(T[2 + i]);
            box = fmaf(d, d, box);
        }
        return loss + cls + 5.0f * box;
    }
    return 0.5f * fmaf(c1, c1, c2 * c2);
}

__global__ __launch_bounds__(THREADS) void yolo_loss_kernel(
    const float* __restrict__ pred,   // [n_cells, 30]
    const float* __restrict__ targ,   // [n_cells, 25]
    long n_cells,
    long n_full,                      // full CPB-cell chunks
    float* __restrict__ out)
{
    __shared__ __align__(16) float sP[STAGES][PRED_F];   // 4 x 9600 B
    __shared__ __align__(16) float sT[STAGES][TARG_F];   // 4 x 8000 B

    const int tid = threadIdx.x;
    const long grid = gridDim.x;

    const unsigned spb = (unsigned)__cvta_generic_to_shared(&sP[0][0]);
    const unsigned stb = (unsigned)__cvta_generic_to_shared(&sT[0][0]);

    // stage one full chunk into slot (exact float4 counts; bases 16-aligned:
    // 9600*ch and 8000*ch are multiples of 16)
    auto stage = [&](int slot, long ch) {
        if (ch < n_full) {
            const float4* gp = reinterpret_cast<const float4*>(pred) + ch * PF4;
            const float4* gt = reinterpret_cast<const float4*>(targ) + ch * TF4;
            unsigned sp = spb + (unsigned)slot * (PRED_F * 4);
            unsigned st = stb + (unsigned)slot * (TARG_F * 4);
            #pragma unroll
            for (int j = 0; j < (PF4 + THREADS - 1) / THREADS; ++j) {  // 5 iters
                int i = j * THREADS + tid;
                if (i < PF4) cp16_l2(sp + i * 16, gp + i);
            }
            #pragma unroll
            for (int j = 0; j < (TF4 + THREADS - 1) / THREADS; ++j) {  // 4 iters
                int i = j * THREADS + tid;
                if (i < TF4) cp16_l2(st + i * 16, gt + i);
            }
        }
        cp_commit();   // uniform group accounting
    };

    // ---- prologue ----
    #pragma unroll
    for (int s = 0; s < STAGES - 1; ++s)
        stage(s, (long)blockIdx.x + (long)s * grid);

    float acc = 0.0f;
    long chunk = blockIdx.x;
    int it = 0;

    while (chunk < n_full) {
        cp_wait<STAGES - 2>();           // chunk 'it' resident
        __syncthreads();

        int slot = it & (STAGES - 1);
        if (tid < CPB)
            acc += cell_loss(sP[slot] + tid * 30, sT[slot] + tid * 25);

        // refill slot (it+STAGES-1)&3 — its old contents (chunk it-1)
        // were consumed before this iteration's barrier
        stage((it + STAGES - 1) & (STAGES - 1), chunk + (long)(STAGES - 1) * grid);

        chunk += grid;
        ++it;
    }

    // ---- ragged tail (n_cells % CPB cells): block 0, direct loads ----
    if (blockIdx.x == 0) {
        for (long cell = n_full * CPB + tid; cell < n_cells; cell += THREADS) {
            float Pl[30], Tl[25];
            #pragma unroll
            for (int i = 0; i < 30; ++i) Pl[i] = __ldg(pred + cell * 30 + i);
            #pragma unroll
            for (int i = 0; i < 25; ++i) Tl[i] = __ldg(targ + cell * 25 + i);
            acc += cell_loss(Pl, Tl);
        }
    }

    // ---- block reduction ----
    #pragma unroll
    for (int off = 16; off > 0; off >>= 1)
        acc += __shfl_xor_sync(0xFFFFFFFFu, acc, off);

    __shared__ float wsum[THREADS / 32];
    const int wid = tid >> 5, lid = tid & 31;
    if (lid == 0) wsum[wid] = acc;
    __syncthreads();

    __shared__ int s_last;
    if (tid == 0) {
        g_partials[blockIdx.x] = wsum[0] + wsum[1] + wsum[2] + wsum[3];
        __threadfence();
        unsigned old = atomicInc(&g_count, gridDim.x - 1);
        s_last = (old == gridDim.x - 1) ? 1 : 0;
    }
    __syncthreads();

    if (s_last) {
        __threadfence();
        double d = 0.0;
        for (int i = tid; i < (int)gridDim.x; i += THREADS)
            d += (double)__ldcg(&g_partials[i]);
        #pragma unroll
        for (int off = 16; off > 0; off >>= 1)
            d += __shfl_xor_sync(0xFFFFFFFFu, d, off);
        __shared__ double dsum[THREADS / 32];
        if (lid == 0) dsum[wid] = d;
        __syncthreads();
        if (tid == 0)
            out[0] = (float)(dsum[0] + dsum[1] + dsum[2] + dsum[3]);
    }
}

extern "C" void kernel_launch(void* const* d_in, const int* in_sizes, int n_in,
                              void* d_out, int out_size) {
    const float* pred = (const float*)d_in[0];   // [B, 1470]
    const float* targ = (const float*)d_in[1];   // [B, 1225]
    float* out = (float*)d_out;

    long B = (long)in_sizes[0] / 1470;
    long n_cells = B * 49;
    long n_full = n_cells / CPB;                 // 10035 for B=16384 (tail 16 cells)

    // balanced grid: all blocks get ceil or ceil-1 chunks
    long blocks;
    if (n_full <= 0) {
        blocks = 1;
    } else {
        long k = (n_full + MAX_RES - 1) / MAX_RES;   // chunks per block (ceil) = 23
        blocks = (n_full + k - 1) / k;               // 437 for 10035
    }
    if (blocks > MAX_PART) blocks = MAX_PART;

    yolo_loss_kernel<<<(unsigned)blocks, THREADS>>>(pred, targ, n_cells, n_full, out);
}

// round 16
// speedup vs baseline: 1.0621x; 1.0621x over previous
#include <cuda_runtime.h>
#include <cstdint>

#define THREADS 128
#define CPB     128
#define STAGES  4
#define PRED_F  (CPB * 30)        // 3840 floats
#define TARG_F  (CPB * 25)        // 3200 floats
#define PF4     (PRED_F / 4)      // 960 float4
#define TF4     (TARG_F / 4)      // 800 float4
#define MAX_RES 296               // 2 blocks/SM x 148 SMs
#define MAX_PART 2048

__device__ float g_partials[MAX_PART];
__device__ unsigned int g_count = 0;   // wraps to 0 each replay via atomicInc

__device__ __forceinline__ void cp16_l2(unsigned smem_addr, const void* gptr) {
    asm volatile("cp.async.cg.shared.global.L2::256B [%0], [%1], 16;"
                 :: "r"(smem_addr), "l"(gptr) : "memory");
}
__device__ __forceinline__ void cp_commit() {
    asm volatile("cp.async.commit_group;" ::: "memory");
}
template <int N>
__device__ __forceinline__ void cp_wait() {
    asm volatile("cp.async.wait_group %0;" :: "n"(N) : "memory");
}

__device__ __forceinline__ float cell_loss(const float* P, const float* T) {
    float c1 = P[4], c2 = P[9], c = T[4];
    bool present = (c == 1.0f);
    bool r1 = (c1 > c2);
    if (present) {
        float dobj = (r1 ? c1 : c2) - c;
        float loss = dobj * dobj;
        float cls = 0.0f;
        #pragma unroll
        for (int i = 0; i < 20; ++i) {
            float d = P[10 + i] - T[5 + i];
            cls = fmaf(d, d, cls);
        }
        int o = r1 ? 0 : 5;
        float box = 0.0f;
        #pragma unroll
        for (int i = 0; i < 2; ++i) {
            float d = P[o + i] - T[i];
            box = fmaf(d, d, box);
        }
        #pragma unroll
        for (int i = 0; i < 2; ++i) {
            float d = sqrtf(P[o + 2 + i]) - sqrtf(T[2 + i]);
            box = fmaf(d, d, box);
        }
        return loss + cls + 5.0f * box;
    }
    return 0.5f * fmaf(c1, c1, c2 * c2);
}

__global__ __launch_bounds__(THREADS) void yolo_loss_kernel(
    const float* __restrict__ pred,   // [n_cells, 30]
    const float* __restrict__ targ,   // [n_cells, 25]
    long n_cells,
    long n_full,                      // full 128-cell chunks
    float* __restrict__ out)
{
    __shared__ __align__(16) float sP[STAGES][PRED_F];   // 4 x 15360 B
    __shared__ __align__(16) float sT[STAGES][TARG_F];   // 4 x 12800 B

    const int tid = threadIdx.x;
    const long grid = gridDim.x;

    const unsigned spb = (unsigned)__cvta_generic_to_shared(&sP[0][0]);
    const unsigned stb = (unsigned)__cvta_generic_to_shared(&sT[0][0]);

    // stage one full chunk into slot (all 128 threads; exact float4 counts)
    auto stage = [&](int slot, long ch) {
        if (ch < n_full) {
            const float4* gp = reinterpret_cast<const float4*>(pred) + ch * PF4;
            const float4* gt = reinterpret_cast<const float4*>(targ) + ch * TF4;
            unsigned sp = spb + (unsigned)slot * (PRED_F * 4);
            unsigned st = stb + (unsigned)slot * (TARG_F * 4);
            #pragma unroll
            for (int j = 0; j < PF4 / THREADS + 1; ++j) {      // 960/128 = 7.5
                int i = j * THREADS + tid;
                if (i < PF4) cp16_l2(sp + i * 16, gp + i);
            }
            #pragma unroll
            for (int j = 0; j < TF4 / THREADS + 1; ++j) {      // 800/128 = 6.25
                int i = j * THREADS + tid;
                if (i < TF4) cp16_l2(st + i * 16, gt + i);
            }
        }
        cp_commit();   // uniform group accounting
    };

    // ---- prologue ----
    #pragma unroll
    for (int s = 0; s < STAGES - 1; ++s)
        stage(s, (long)blockIdx.x + (long)s * grid);

    float acc = 0.0f;
    long chunk = blockIdx.x;
    int it = 0;

    while (chunk < n_full) {
        cp_wait<STAGES - 2>();           // chunk 'it' resident
        __syncthreads();

        int slot = it & (STAGES - 1);
        acc += cell_loss(sP[slot] + tid * 30, sT[slot] + tid * 25);

        // refill slot (it+STAGES-1)%STAGES — its old contents (chunk it-1)
        // were consumed before this iteration's barrier
        stage((it + STAGES - 1) & (STAGES - 1), chunk + (long)(STAGES - 1) * grid);

        chunk += grid;
        ++it;
    }

    // ---- ragged tail: block 0, direct loads ----
    if (blockIdx.x == 0) {
        for (long cell = n_full * CPB + tid; cell < n_cells; cell += THREADS) {
            float Pl[30], Tl[25];
            #pragma unroll
            for (int i = 0; i < 30; ++i) Pl[i] = __ldg(pred + cell * 30 + i);
            #pragma unroll
            for (int i = 0; i < 25; ++i) Tl[i] = __ldg(targ + cell * 25 + i);
            acc += cell_loss(Pl, Tl);
        }
    }

    // ---- block reduction ----
    #pragma unroll
    for (int off = 16; off > 0; off >>= 1)
        acc += __shfl_xor_sync(0xFFFFFFFFu, acc, off);

    __shared__ float wsum[THREADS / 32];
    const int wid = tid >> 5, lid = tid & 31;
    if (lid == 0) wsum[wid] = acc;
    __syncthreads();

    __shared__ int s_last;
    if (tid == 0) {
        g_partials[blockIdx.x] = wsum[0] + wsum[1] + wsum[2] + wsum[3];
        __threadfence();
        unsigned old = atomicInc(&g_count, gridDim.x - 1);
        s_last = (old == gridDim.x - 1) ? 1 : 0;
    }
    __syncthreads();

    if (s_last) {
        __threadfence();
        double d = 0.0;
        for (int i = tid; i < (int)gridDim.x; i += THREADS)
            d += (double)__ldcg(&g_partials[i]);
        #pragma unroll
        for (int off = 16; off > 0; off >>= 1)
            d += __shfl_xor_sync(0xFFFFFFFFu, d, off);
        __shared__ double dsum[THREADS / 32];
        if (lid == 0) dsum[wid] = d;
        __syncthreads();
        if (tid == 0)
            out[0] = (float)(dsum[0] + dsum[1] + dsum[2] + dsum[3]);
    }
}

extern "C" void kernel_launch(void* const* d_in, const int* in_sizes, int n_in,
                              void* d_out, int out_size) {
    const float* pred = (const float*)d_in[0];   // [B, 1470]
    const float* targ = (const float*)d_in[1];   // [B, 1225]
    float* out = (float*)d_out;

    long B = (long)in_sizes[0] / 1470;
    long n_cells = B * 49;
    long n_full = n_cells / CPB;                 // 6272 for B=16384

    // balanced grid: all blocks get ceil or ceil-1 chunks with minimal spread
    long blocks;
    if (n_full <= 0) {
        blocks = 1;
    } else {
        long k = (n_full + MAX_RES - 1) / MAX_RES;   // chunks per block (ceil)
        blocks = (n_full + k - 1) / k;               // 286 for 6272
    }
    if (blocks > MAX_PART) blocks = MAX_PART;

    yolo_loss_kernel<<<(unsigned)blocks, THREADS>>>(pred, targ, n_cells, n_full, out);
}